// round 1
// baseline (speedup 1.0000x reference)
#include <cuda_runtime.h>

// Problem constants
#define B_DIM   8192
#define IN_DIM  1024
#define OUT_DIM 1024
#define ORD     8              // ORDER+1 powers per input
#define KTOT    (IN_DIM * ORD) // 8192 reduction length

// Scratch: tanh(x * r), [B_DIM][IN_DIM]
__device__ float g_t[B_DIM * IN_DIM];

// ---------------------------------------------------------------------------
// Kernel 1: t = tanh(x * tanh_range), vectorized float4
// ---------------------------------------------------------------------------
__global__ void tanh_precompute_kernel(const float* __restrict__ x,
                                       const float* __restrict__ rp) {
    const float r = *rp;
    int idx = blockIdx.x * blockDim.x + threadIdx.x;
    int n4 = (B_DIM * IN_DIM) / 4;
    if (idx < n4) {
        float4 v = reinterpret_cast<const float4*>(x)[idx];
        float4 o;
        o.x = tanhf(v.x * r);
        o.y = tanhf(v.y * r);
        o.z = tanhf(v.z * r);
        o.w = tanhf(v.w * r);
        reinterpret_cast<float4*>(g_t)[idx] = o;
    }
}

// ---------------------------------------------------------------------------
// Kernel 2: fused poly-expansion + fp32 GEMM
//   out[b, j] = sum_{kk} A[b, kk] * coef[j, kk],  kk = i*8 + k,  A = t^k
// Tiles: BM=128, BN=128, BK=32 (4 inputs * 8 powers), 256 threads, 8x8/thread
// ---------------------------------------------------------------------------
#define BM 128
#define BN 128
#define BK 32
#define TM 8
#define TN 8

__global__ __launch_bounds__(256, 2)
void taylor_gemm_kernel(const float* __restrict__ coef,
                        float* __restrict__ out) {
    __shared__ float sA[BK][BM];
    __shared__ float sB[BK][BN];

    const int tid = threadIdx.x;
    const int bm0 = blockIdx.y * BM;
    const int bn0 = blockIdx.x * BN;

    // compute-phase thread tile: 16x16 thread grid, each 8x8 outputs
    const int tx = tid & 15;   // N direction
    const int ty = tid >> 4;   // M direction

    // A-generation mapping: 256 threads = 128 rows x 2 halves (2 inputs each)
    const int arow  = tid & 127;
    const int ahalf = tid >> 7;          // 0 or 1

    // B-load mapping: tid -> (kk-group, j-base)
    const int kg = (tid & 7) * 4;        // 0,4,...,28
    const int jb = tid >> 3;             // 0..31

    float acc[TM][TN];
#pragma unroll
    for (int m = 0; m < TM; m++)
#pragma unroll
        for (int n = 0; n < TN; n++) acc[m][n] = 0.f;

#pragma unroll 1
    for (int kt = 0; kt < KTOT / BK; ++kt) {
        const int i0 = kt * (BK / ORD);  // first input index of this K-tile (4 inputs)

        // ---- generate A tile: powers of t, stored K-major [BK][BM] ----
        {
            const float2 tv = *reinterpret_cast<const float2*>(
                &g_t[(size_t)(bm0 + arow) * IN_DIM + i0 + ahalf * 2]);
            float p = 1.f;
#pragma unroll
            for (int k = 0; k < ORD; k++) {
                sA[(ahalf * 2 + 0) * ORD + k][arow] = p;
                p *= tv.x;
            }
            p = 1.f;
#pragma unroll
            for (int k = 0; k < ORD; k++) {
                sA[(ahalf * 2 + 1) * ORD + k][arow] = p;
                p *= tv.y;
            }
        }

        // ---- load B tile: coef rows are K-contiguous; transpose into [BK][BN] ----
        {
#pragma unroll
            for (int pass = 0; pass < 4; ++pass) {
                const int j = jb + pass * 32;
                float4 v = *reinterpret_cast<const float4*>(
                    &coef[(size_t)(bn0 + j) * KTOT + kt * BK + kg]);
                sB[kg + 0][j] = v.x;
                sB[kg + 1][j] = v.y;
                sB[kg + 2][j] = v.z;
                sB[kg + 3][j] = v.w;
            }
        }

        __syncthreads();

        // ---- inner product ----
#pragma unroll
        for (int kk = 0; kk < BK; ++kk) {
            float a[TM], b[TN];
            *reinterpret_cast<float4*>(&a[0]) =
                *reinterpret_cast<const float4*>(&sA[kk][ty * TM]);
            *reinterpret_cast<float4*>(&a[4]) =
                *reinterpret_cast<const float4*>(&sA[kk][ty * TM + 4]);
            *reinterpret_cast<float4*>(&b[0]) =
                *reinterpret_cast<const float4*>(&sB[kk][tx * TN]);
            *reinterpret_cast<float4*>(&b[4]) =
                *reinterpret_cast<const float4*>(&sB[kk][tx * TN + 4]);
#pragma unroll
            for (int m = 0; m < TM; m++)
#pragma unroll
                for (int n = 0; n < TN; n++)
                    acc[m][n] += a[m] * b[n];
        }

        __syncthreads();
    }

    // ---- epilogue: coalesced float4 stores ----
#pragma unroll
    for (int m = 0; m < TM; m++) {
        float4* o = reinterpret_cast<float4*>(
            &out[(size_t)(bm0 + ty * TM + m) * OUT_DIM + bn0 + tx * TN]);
        o[0] = *reinterpret_cast<float4*>(&acc[m][0]);
        o[1] = *reinterpret_cast<float4*>(&acc[m][4]);
    }
}

// ---------------------------------------------------------------------------
// Launch
// ---------------------------------------------------------------------------
extern "C" void kernel_launch(void* const* d_in, const int* in_sizes, int n_in,
                              void* d_out, int out_size) {
    const float* x    = (const float*)d_in[0];   // [8192, 1024] f32
    const float* rng  = (const float*)d_in[1];   // scalar f32
    const float* coef = (const float*)d_in[2];   // [1024, 1024, 8] f32
    float* out        = (float*)d_out;           // [8192, 1024] f32

    (void)in_sizes; (void)n_in; (void)out_size;

    // 1) tanh precompute: 8.4M elements / 4 per thread
    {
        int n4 = (B_DIM * IN_DIM) / 4;
        int threads = 256;
        int blocks = (n4 + threads - 1) / threads;
        tanh_precompute_kernel<<<blocks, threads>>>(x, rng);
    }

    // 2) fused poly + GEMM
    {
        dim3 grid(OUT_DIM / BN, B_DIM / BM);  // (8, 64)
        taylor_gemm_kernel<<<grid, 256>>>(coef, out);
    }
}

// round 3
// speedup vs baseline: 3.0380x; 3.0380x over previous
#include <cuda_runtime.h>
#include <cstdint>

// Problem constants
#define B_DIM   8192
#define IN_DIM  1024
#define OUT_DIM 1024
#define ORD     8              // ORDER+1 powers per input
#define KTOT    (IN_DIM * ORD) // 8192 reduction length

#define BM 128
#define BN 128
#define BK 32
#define NKT (KTOT / BK)        // 256 K-tiles
#define SA_STRIDE (BM + 8)     // row stride 136 floats -> 8 banks apart per row
#define SB_STRIDE (BN + 8)

// Scratch: tanh(x * r), [B_DIM][IN_DIM]
__device__ float g_t[B_DIM * IN_DIM];

// ---------------------------------------------------------------------------
// Kernel 1: t = tanh(x * tanh_range), vectorized float4
// ---------------------------------------------------------------------------
__global__ void tanh_precompute_kernel(const float* __restrict__ x,
                                       const float* __restrict__ rp) {
    const float r = *rp;
    int idx = blockIdx.x * blockDim.x + threadIdx.x;
    int n4 = (B_DIM * IN_DIM) / 4;
    if (idx < n4) {
        float4 v = reinterpret_cast<const float4*>(x)[idx];
        float4 o;
        o.x = tanhf(v.x * r);
        o.y = tanhf(v.y * r);
        o.z = tanhf(v.z * r);
        o.w = tanhf(v.w * r);
        reinterpret_cast<float4*>(g_t)[idx] = o;
    }
}

// ---------------------------------------------------------------------------
// TF32 helpers
// ---------------------------------------------------------------------------
__device__ __forceinline__ uint32_t f2tf32(float f) {
    uint32_t r;
    asm("cvt.rna.tf32.f32 %0, %1;" : "=r"(r) : "f"(f));
    return r;
}

__device__ __forceinline__ void mma_tf32(float c[4],
                                         const uint32_t a[4],
                                         uint32_t b0, uint32_t b1) {
    asm volatile(
        "mma.sync.aligned.m16n8k8.row.col.f32.tf32.tf32.f32 "
        "{%0,%1,%2,%3}, {%4,%5,%6,%7}, {%8,%9}, {%0,%1,%2,%3};\n"
        : "+f"(c[0]), "+f"(c[1]), "+f"(c[2]), "+f"(c[3])
        : "r"(a[0]), "r"(a[1]), "r"(a[2]), "r"(a[3]),
          "r"(b0), "r"(b1));
}

// ---------------------------------------------------------------------------
// Kernel 2: fused poly-expansion + TF32 tensor-core GEMM
//   out[b, j] = sum_{kk} A[b, kk] * coef[j, kk],  kk = i*8 + k,  A = t^k
// 128x128x32 tiles, 8 warps, warp tile 64x32 (4x4 grid of m16n8k8 mma)
// ---------------------------------------------------------------------------
__global__ __launch_bounds__(256, 2)
void taylor_mma_kernel(const float* __restrict__ coef,
                       float* __restrict__ out) {
    __shared__ uint32_t sA[BK][SA_STRIDE];   // tf32 bits, K-major
    __shared__ uint32_t sB[BK][SB_STRIDE];   // tf32 bits, K-major (col-xor'd)

    const int tid  = threadIdx.x;
    const int lane = tid & 31;
    const int warp = tid >> 5;
    const int warp_m = warp & 1;     // 2 warps over M (64 rows each)
    const int warp_n = warp >> 1;    // 4 warps over N (32 cols each)
    const int gid = lane >> 2;       // group id (0..7)
    const int tig = lane & 3;        // thread in group (0..3)

    const int bm0 = blockIdx.y * BM;
    const int bn0 = blockIdx.x * BN;

    // A-generation mapping: 256 threads = 128 rows x 2 halves (2 inputs each)
    const int arow  = tid & 127;
    const int ahalf = tid >> 7;
    const float* tRow = &g_t[(size_t)(bm0 + arow) * IN_DIM];

    // B-load mapping: 2 threads per coef row, 16 consecutive K-floats each
    const int jb = tid >> 1;                 // 0..127
    const int kh = (tid & 1) * 16;           // 0 or 16
    const int jp = jb ^ kh;                  // physical smem column (xor-swizzle)
    const float* bBase = &coef[(size_t)(bn0 + jb) * KTOT + kh];

    float acc[4][4][4];
#pragma unroll
    for (int mt = 0; mt < 4; mt++)
#pragma unroll
        for (int nt = 0; nt < 4; nt++)
#pragma unroll
            for (int c = 0; c < 4; c++) acc[mt][nt][c] = 0.f;

    float2 tv;        // prefetched tanh values (2 inputs)
    float4 bPre[4];   // prefetched 16 coef floats

    // ---- prologue: prefetch kt=0, fill smem ----
    tv = *reinterpret_cast<const float2*>(&tRow[0 + ahalf * 2]);
#pragma unroll
    for (int q = 0; q < 4; q++)
        bPre[q] = *reinterpret_cast<const float4*>(bBase + q * 4);

    {
        float p = 1.f;
#pragma unroll
        for (int k = 0; k < ORD; k++) { sA[(ahalf * 2 + 0) * ORD + k][arow] = f2tf32(p); p *= tv.x; }
        p = 1.f;
#pragma unroll
        for (int k = 0; k < ORD; k++) { sA[(ahalf * 2 + 1) * ORD + k][arow] = f2tf32(p); p *= tv.y; }
#pragma unroll
        for (int q = 0; q < 4; q++) {
            sB[kh + q * 4 + 0][jp] = f2tf32(bPre[q].x);
            sB[kh + q * 4 + 1][jp] = f2tf32(bPre[q].y);
            sB[kh + q * 4 + 2][jp] = f2tf32(bPre[q].z);
            sB[kh + q * 4 + 3][jp] = f2tf32(bPre[q].w);
        }
    }
    __syncthreads();

#pragma unroll 1
    for (int kt = 0; kt < NKT; ++kt) {
        // ---- prefetch next tile into registers ----
        if (kt + 1 < NKT) {
            tv = *reinterpret_cast<const float2*>(&tRow[(kt + 1) * 4 + ahalf * 2]);
            const float* bp = bBase + (size_t)(kt + 1) * BK;
#pragma unroll
            for (int q = 0; q < 4; q++)
                bPre[q] = *reinterpret_cast<const float4*>(bp + q * 4);
        }

        // ---- mma on current smem tile ----
#pragma unroll
        for (int ks = 0; ks < 4; ++ks) {
            const int k0 = ks * 8;
            const int nxor = k0 & 16;        // column xor for this K-range

            uint32_t a[4][4];
#pragma unroll
            for (int mt = 0; mt < 4; mt++) {
                const int m0 = warp_m * 64 + mt * 16;
                a[mt][0] = sA[k0 + tig][m0 + gid];
                a[mt][1] = sA[k0 + tig][m0 + gid + 8];
                a[mt][2] = sA[k0 + tig + 4][m0 + gid];
                a[mt][3] = sA[k0 + tig + 4][m0 + gid + 8];
            }
#pragma unroll
            for (int nt = 0; nt < 4; nt++) {
                const int n0 = warp_n * 32 + nt * 8;
                const int np = (n0 ^ nxor) + gid;
                const uint32_t b0 = sB[k0 + tig][np];
                const uint32_t b1 = sB[k0 + tig + 4][np];
#pragma unroll
                for (int mt = 0; mt < 4; mt++)
                    mma_tf32(acc[mt][nt], a[mt], b0, b1);
            }
        }

        __syncthreads();

        // ---- convert + store prefetched tile into smem ----
        if (kt + 1 < NKT) {
            float p = 1.f;
#pragma unroll
            for (int k = 0; k < ORD; k++) { sA[(ahalf * 2 + 0) * ORD + k][arow] = f2tf32(p); p *= tv.x; }
            p = 1.f;
#pragma unroll
            for (int k = 0; k < ORD; k++) { sA[(ahalf * 2 + 1) * ORD + k][arow] = f2tf32(p); p *= tv.y; }
#pragma unroll
            for (int q = 0; q < 4; q++) {
                sB[kh + q * 4 + 0][jp] = f2tf32(bPre[q].x);
                sB[kh + q * 4 + 1][jp] = f2tf32(bPre[q].y);
                sB[kh + q * 4 + 2][jp] = f2tf32(bPre[q].z);
                sB[kh + q * 4 + 3][jp] = f2tf32(bPre[q].w);
            }
            __syncthreads();
        }
    }

    // ---- epilogue: float2 stores ----
#pragma unroll
    for (int mt = 0; mt < 4; mt++) {
        const int m0 = bm0 + warp_m * 64 + mt * 16;
#pragma unroll
        for (int nt = 0; nt < 4; nt++) {
            const int n0 = bn0 + warp_n * 32 + nt * 8;
            float2 v01 = make_float2(acc[mt][nt][0], acc[mt][nt][1]);
            float2 v23 = make_float2(acc[mt][nt][2], acc[mt][nt][3]);
            *reinterpret_cast<float2*>(&out[(size_t)(m0 + gid) * OUT_DIM + n0 + tig * 2]) = v01;
            *reinterpret_cast<float2*>(&out[(size_t)(m0 + gid + 8) * OUT_DIM + n0 + tig * 2]) = v23;
        }
    }
}

// ---------------------------------------------------------------------------
// Launch
// ---------------------------------------------------------------------------
extern "C" void kernel_launch(void* const* d_in, const int* in_sizes, int n_in,
                              void* d_out, int out_size) {
    const float* x    = (const float*)d_in[0];   // [8192, 1024] f32
    const float* rng  = (const float*)d_in[1];   // scalar f32
    const float* coef = (const float*)d_in[2];   // [1024, 1024, 8] f32
    float* out        = (float*)d_out;           // [8192, 1024] f32

    (void)in_sizes; (void)n_in; (void)out_size;

    // 1) tanh precompute
    {
        int n4 = (B_DIM * IN_DIM) / 4;
        int threads = 256;
        int blocks = (n4 + threads - 1) / threads;
        tanh_precompute_kernel<<<blocks, threads>>>(x, rng);
    }

    // 2) fused poly + TF32 tensor-core GEMM
    {
        dim3 grid(OUT_DIM / BN, B_DIM / BM);  // (8, 64)
        taylor_mma_kernel<<<grid, 256>>>(coef, out);
    }
}

// round 6
// speedup vs baseline: 3.4213x; 1.1262x over previous
#include <cuda_runtime.h>
#include <cuda_fp16.h>
#include <cstdint>

// Problem constants
#define B_DIM   8192
#define IN_DIM  1024
#define OUT_DIM 1024
#define ORD     8              // ORDER+1 powers per input
#define KTOT    (IN_DIM * ORD) // 8192 reduction length

#define BM 128
#define BN 128
#define BK 32                  // 4 inputs * 8 powers per K-tile
#define NKT (KTOT / BK)        // 256 K-tiles

// Scratch: tanh(x * r), [B_DIM][IN_DIM]
__device__ float g_t[B_DIM * IN_DIM];

// ---------------------------------------------------------------------------
// Kernel 1: t = tanh(x * tanh_range)
// ---------------------------------------------------------------------------
__global__ void tanh_precompute_kernel(const float* __restrict__ x,
                                       const float* __restrict__ rp) {
    const float r = *rp;
    int idx = blockIdx.x * blockDim.x + threadIdx.x;
    int n4 = (B_DIM * IN_DIM) / 4;
    if (idx < n4) {
        float4 v = reinterpret_cast<const float4*>(x)[idx];
        float4 o;
        o.x = tanhf(v.x * r);
        o.y = tanhf(v.y * r);
        o.z = tanhf(v.z * r);
        o.w = tanhf(v.w * r);
        reinterpret_cast<float4*>(g_t)[idx] = o;
    }
}

// ---------------------------------------------------------------------------
// Helpers
// ---------------------------------------------------------------------------
__device__ __forceinline__ uint32_t smem_u32(const void* p) {
    uint32_t a;
    asm("{ .reg .u64 t; cvta.to.shared.u64 t, %1; cvt.u32.u64 %0, t; }"
        : "=r"(a) : "l"(p));
    return a;
}
__device__ __forceinline__ uint32_t packh2(float lo, float hi) {
    __half2 h = __floats2half2_rn(lo, hi);
    return *reinterpret_cast<uint32_t*>(&h);
}
__device__ __forceinline__ void ldsm4(uint32_t* f, uint32_t addr) {
    asm volatile("ldmatrix.sync.aligned.m8n8.x4.shared.b16 {%0,%1,%2,%3}, [%4];"
                 : "=r"(f[0]), "=r"(f[1]), "=r"(f[2]), "=r"(f[3])
                 : "r"(addr) : "memory");
}
__device__ __forceinline__ void mma16816(float* c, const uint32_t* a,
                                         uint32_t b0, uint32_t b1) {
    asm("mma.sync.aligned.m16n8k16.row.col.f32.f16.f16.f32 "
        "{%0,%1,%2,%3}, {%4,%5,%6,%7}, {%8,%9}, {%0,%1,%2,%3};"
        : "+f"(c[0]), "+f"(c[1]), "+f"(c[2]), "+f"(c[3])
        : "r"(a[0]), "r"(a[1]), "r"(a[2]), "r"(a[3]), "r"(b0), "r"(b1));
}

// ---------------------------------------------------------------------------
// Kernel 2: fused poly-expansion + fp16 m16n8k16 tensor-core GEMM
//
// A tile (smem): [128 rows][32 halfs] = 8 KB. Row = 4 inputs * 8 powers.
//   Stored as 16B quads: quad(row, q) at uint4 index row*4 + (q ^ ((row>>1)&3)).
//   Quad q of a row = halfs [t_q^0 .. t_q^7] (powers of input q, h2-packed).
// B tile (smem): k-paired h2 [16 qrows][128 cols] = 8 KB.
//   Bp[q][j] = h2(coef[j][2q], coef[j][2q+1]); word index q*128 + (j ^ ((q&3)<<3)).
// 8 warps, warp tile 64x32 (2x4), 4x4 m16n8k16 per warp per K16-step.
// ---------------------------------------------------------------------------
__global__ __launch_bounds__(256, 2)
void taylor_hmma_kernel(const float* __restrict__ coef,
                        float* __restrict__ out) {
    __shared__ __align__(16) uint32_t sA[2][2048];   // 2 x 8 KB
    __shared__ __align__(16) uint32_t sB[2][2048];   // 2 x 8 KB

    const int tid  = threadIdx.x;
    const int lane = tid & 31;
    const int warp = tid >> 5;
    const int warp_m = warp & 1;    // 2 warps over M (64 rows)
    const int warp_n = warp >> 1;   // 4 warps over N (32 cols)
    const int gid = lane >> 2;
    const int tig = lane & 3;

    const int bm0 = blockIdx.y * BM;
    const int bn0 = blockIdx.x * BN;

    // ---- producer roles ----
    // A: thread -> (row, input-pair): 2 power series
    const int arow  = tid & 127;
    const int ipair = tid >> 7;                  // inputs 2*ipair, 2*ipair+1
    const float* tptr = &g_t[(size_t)(bm0 + arow) * IN_DIM + ipair * 2];
    const int swA = (arow >> 1) & 3;

    // B: thread -> (col j, k-half): 16 consecutive K floats
    const int jcol = tid & 127;
    const int kh   = tid >> 7;                   // warp-uniform
    const float* cptr = &coef[(size_t)(bn0 + jcol) * KTOT + kh * 16];

    // ---- ldmatrix lane geometry (A consumer) ----
    const int lrow = lane & 15;                  // row within 16
    const int lkc  = lane >> 4;                  // 8-col block -> input parity
    const int lsw  = (lrow >> 1) & 3;

    float acc[4][4][4];
#pragma unroll
    for (int mt = 0; mt < 4; mt++)
#pragma unroll
        for (int nt = 0; nt < 4; nt++)
#pragma unroll
            for (int c = 0; c < 4; c++) acc[mt][nt][c] = 0.f;

    float2 tv;
    float4 cf[4];

    // ---- produce a tile into buffer `buf` from registers tv/cf ----
    auto produce = [&](int buf) {
        uint4* pA = reinterpret_cast<uint4*>(&sA[buf][0]);
        {
            float t = tv.x;
            float t2 = t * t, t3 = t2 * t, t4 = t2 * t2;
            float t5 = t4 * t, t6 = t3 * t3, t7 = t4 * t3;
            uint4 qv;
            qv.x = packh2(1.f, t);  qv.y = packh2(t2, t3);
            qv.z = packh2(t4, t5);  qv.w = packh2(t6, t7);
            pA[arow * 4 + ((ipair * 2) ^ swA)] = qv;
        }
        {
            float t = tv.y;
            float t2 = t * t, t3 = t2 * t, t4 = t2 * t2;
            float t5 = t4 * t, t6 = t3 * t3, t7 = t4 * t3;
            uint4 qv;
            qv.x = packh2(1.f, t);  qv.y = packh2(t2, t3);
            qv.z = packh2(t4, t5);  qv.w = packh2(t6, t7);
            pA[arow * 4 + ((ipair * 2 + 1) ^ swA)] = qv;
        }
#pragma unroll
        for (int q = 0; q < 4; q++) {
            int q0 = kh * 8 + q * 2, q1 = q0 + 1;
            sB[buf][q0 * 128 + (jcol ^ ((q0 & 3) << 3))] = packh2(cf[q].x, cf[q].y);
            sB[buf][q1 * 128 + (jcol ^ ((q1 & 3) << 3))] = packh2(cf[q].z, cf[q].w);
        }
    };

    // ---- prologue: tile 0 ----
    tv = *reinterpret_cast<const float2*>(tptr);
#pragma unroll
    for (int q = 0; q < 4; q++)
        cf[q] = *reinterpret_cast<const float4*>(cptr + q * 4);
    produce(0);
    __syncthreads();

    const uint32_t aBase[2] = { smem_u32(&sA[0][0]), smem_u32(&sA[1][0]) };

#pragma unroll 1
    for (int kt = 0; kt < NKT; ++kt) {
        const int cur = kt & 1;
        const bool more = (kt + 1 < NKT);

        // prefetch next tile's gmem data into registers
        if (more) {
            tv = *reinterpret_cast<const float2*>(tptr + (size_t)(kt + 1) * 4);
            const float* cp = cptr + (size_t)(kt + 1) * BK;
#pragma unroll
            for (int q = 0; q < 4; q++)
                cf[q] = *reinterpret_cast<const float4*>(cp + q * 4);
        }

        // ---- consume current buffer ----
        const uint32_t* sBb = &sB[cur][0];
#pragma unroll
        for (int ks = 0; ks < 2; ++ks) {
            uint32_t af[4][4];
#pragma unroll
            for (int mt = 0; mt < 4; mt++) {
                const int row_g = warp_m * 64 + mt * 16 + lrow;
                const int qp = (ks * 2 + lkc) ^ lsw;
                ldsm4(af[mt], aBase[cur] + (uint32_t)(row_g * 64 + qp * 16));
            }
#pragma unroll
            for (int nt = 0; nt < 4; nt++) {
                const int col = warp_n * 32 + nt * 8 + gid;
                const int q0 = ks * 8 + tig;
                const int widx = q0 * 128 + (col ^ (tig << 3));
                const uint32_t b0 = sBb[widx];
                const uint32_t b1 = sBb[widx + 4 * 128];
#pragma unroll
                for (int mt = 0; mt < 4; mt++)
                    mma16816(acc[mt][nt], af[mt], b0, b1);
            }
        }

        // ---- produce next tile into other buffer ----
        if (more) produce(cur ^ 1);
        __syncthreads();
    }

    // ---- epilogue: float2 stores ----
#pragma unroll
    for (int mt = 0; mt < 4; mt++) {
        const int row = bm0 + warp_m * 64 + mt * 16 + gid;
#pragma unroll
        for (int nt = 0; nt < 4; nt++) {
            const int col = bn0 + warp_n * 32 + nt * 8 + tig * 2;
            *reinterpret_cast<float2*>(&out[(size_t)row * OUT_DIM + col]) =
                make_float2(acc[mt][nt][0], acc[mt][nt][1]);
            *reinterpret_cast<float2*>(&out[(size_t)(row + 8) * OUT_DIM + col]) =
                make_float2(acc[mt][nt][2], acc[mt][nt][3]);
        }
    }
}

// ---------------------------------------------------------------------------
// Launch
// ---------------------------------------------------------------------------
extern "C" void kernel_launch(void* const* d_in, const int* in_sizes, int n_in,
                              void* d_out, int out_size) {
    const float* x    = (const float*)d_in[0];   // [8192, 1024] f32
    const float* rng  = (const float*)d_in[1];   // scalar f32
    const float* coef = (const float*)d_in[2];   // [1024, 1024, 8] f32
    float* out        = (float*)d_out;           // [8192, 1024] f32

    (void)in_sizes; (void)n_in; (void)out_size;

    // 1) tanh precompute
    {
        int n4 = (B_DIM * IN_DIM) / 4;
        int threads = 256;
        int blocks = (n4 + threads - 1) / threads;
        tanh_precompute_kernel<<<blocks, threads>>>(x, rng);
    }

    // 2) fused poly + fp16 tensor-core GEMM
    {
        dim3 grid(OUT_DIM / BN, B_DIM / BM);  // (8, 64)
        taylor_hmma_kernel<<<grid, 256>>>(coef, out);
    }
}

// round 8
// speedup vs baseline: 7.6599x; 2.2389x over previous
#include <cuda_runtime.h>
#include <cuda_fp16.h>
#include <cstdint>

// Problem constants
#define B_DIM   8192
#define IN_DIM  1024
#define OUT_DIM 1024
#define ORD     8              // ORDER+1 powers per input
#define KTOT    (IN_DIM * ORD) // 8192 reduction length

#define BM 128
#define BN 128
#define BK 32                  // 4 inputs * 8 powers per K-tile
#define NKT (KTOT / BK)        // 256 K-tiles
#define NBM (B_DIM / BM)       // 64
#define NBN (OUT_DIM / BN)     // 8

#define STAGES 3
#define TILE_U4 512            // 8 KB per operand tile = 512 uint4

// Precomputed smem-image scratch
//   gA_img[bm][kt] = 8 KB A-tile image (quad-swizzled fp16 powers)   -> 128 MB
//   gB_img[bn][kt] = 8 KB B-tile image (xor-swizzled k-paired half2) ->  16 MB
__device__ __align__(16) uint4 gA_img[(size_t)NBM * NKT * TILE_U4];
__device__ __align__(16) uint4 gB_img[(size_t)NBN * NKT * TILE_U4];

// ---------------------------------------------------------------------------
// Helpers
// ---------------------------------------------------------------------------
__device__ __forceinline__ uint32_t smem_u32(const void* p) {
    uint32_t a;
    asm("{ .reg .u64 t; cvta.to.shared.u64 t, %1; cvt.u32.u64 %0, t; }"
        : "=r"(a) : "l"(p));
    return a;
}
__device__ __forceinline__ uint32_t packh2(float lo, float hi) {
    __half2 h = __floats2half2_rn(lo, hi);
    return *reinterpret_cast<uint32_t*>(&h);
}
__device__ __forceinline__ void ldsm4(uint32_t* f, uint32_t addr) {
    asm volatile("ldmatrix.sync.aligned.m8n8.x4.shared.b16 {%0,%1,%2,%3}, [%4];"
                 : "=r"(f[0]), "=r"(f[1]), "=r"(f[2]), "=r"(f[3])
                 : "r"(addr) : "memory");
}
__device__ __forceinline__ void mma16816(float* c, const uint32_t* a,
                                         uint32_t b0, uint32_t b1) {
    asm("mma.sync.aligned.m16n8k16.row.col.f32.f16.f16.f32 "
        "{%0,%1,%2,%3}, {%4,%5,%6,%7}, {%8,%9}, {%0,%1,%2,%3};"
        : "+f"(c[0]), "+f"(c[1]), "+f"(c[2]), "+f"(c[3])
        : "r"(a[0]), "r"(a[1]), "r"(a[2]), "r"(a[3]), "r"(b0), "r"(b1));
}
__device__ __forceinline__ void cp16(uint32_t smaddr, const void* g) {
    asm volatile("cp.async.cg.shared.global [%0], [%1], 16;"
                 :: "r"(smaddr), "l"(g) : "memory");
}
__device__ __forceinline__ void cp_commit() {
    asm volatile("cp.async.commit_group;" ::: "memory");
}
__device__ __forceinline__ void cp_wait1() {
    asm volatile("cp.async.wait_group 1;" ::: "memory");
}
__device__ __forceinline__ void cp_wait0() {
    asm volatile("cp.async.wait_group 0;" ::: "memory");
}

// ---------------------------------------------------------------------------
// Prep kernel A: tanh + powers -> quad-swizzled fp16 tile image
//   image uint4 idx (in tile): row*4 + (q ^ ((row>>1)&3))
//   content: half2 pairs {1,t},{t2,t3},{t4,t5},{t6,t7} of t = tanh(x*r)
// ---------------------------------------------------------------------------
__global__ void prep_a_kernel(const float* __restrict__ x,
                              const float* __restrict__ rp) {
    const float r = *rp;
    const int kt = blockIdx.x;
    const int bm = blockIdx.y;
    const int tid = threadIdx.x;
    const int row = tid >> 2;
    const int q   = tid & 3;

    const float xv = x[(size_t)(bm * BM + row) * IN_DIM + kt * 4 + q];
    const float t  = tanhf(xv * r);
    const float t2 = t * t, t3 = t2 * t, t4 = t2 * t2;
    const float t5 = t4 * t, t6 = t3 * t3, t7 = t4 * t3;

    uint4 qv;
    qv.x = packh2(1.f, t);  qv.y = packh2(t2, t3);
    qv.z = packh2(t4, t5);  qv.w = packh2(t6, t7);

    gA_img[((size_t)bm * NKT + kt) * TILE_U4 + row * 4 + (q ^ ((row >> 1) & 3))] = qv;
}

// ---------------------------------------------------------------------------
// Prep kernel B: coef -> xor-swizzled k-paired half2 tile image
//   word idx (in tile): q0*128 + (j ^ ((q0&3)<<3)), q0 = k-pair index 0..15
//   content: half2(coef[j][kt*32+2*q0], coef[j][kt*32+2*q0+1])
// ---------------------------------------------------------------------------
__global__ void prep_b_kernel(const float* __restrict__ coef) {
    const int kt = blockIdx.x;
    const int bn = blockIdx.y;
    const int tid = threadIdx.x;
    const int s = tid & 3;        // k-octet slot (8 floats)
    const int j = tid >> 2;       // column 0..127

    const float* cp = &coef[(size_t)(bn * BN + j) * KTOT + kt * BK + s * 8];
    const float4 c0 = *reinterpret_cast<const float4*>(cp);
    const float4 c1 = *reinterpret_cast<const float4*>(cp + 4);

    uint32_t* gw = reinterpret_cast<uint32_t*>(
        &gB_img[((size_t)bn * NKT + kt) * TILE_U4]);
    const int q0 = s * 4;         // q0&3 == u for u = 0..3
    gw[(q0 + 0) * 128 + (j ^ 0)]  = packh2(c0.x, c0.y);
    gw[(q0 + 1) * 128 + (j ^ 8)]  = packh2(c0.z, c0.w);
    gw[(q0 + 2) * 128 + (j ^ 16)] = packh2(c1.x, c1.y);
    gw[(q0 + 3) * 128 + (j ^ 24)] = packh2(c1.z, c1.w);
}

// ---------------------------------------------------------------------------
// GEMM kernel: 3-stage cp.async fp16 m16n8k16 pipeline
// smem stage layout: [A tile 8KB][B tile 8KB] per stage, 48 KB total
// ---------------------------------------------------------------------------
__global__ __launch_bounds__(256, 2)
void taylor_pipe_kernel(float* __restrict__ out) {
    __shared__ __align__(16) uint4 smem[STAGES][2 * TILE_U4];

    const int tid  = threadIdx.x;
    const int lane = tid & 31;
    const int warp = tid >> 5;
    const int warp_m = warp & 1;    // 2 warps over M (64 rows)
    const int warp_n = warp >> 1;   // 4 warps over N (32 cols)
    const int gid = lane >> 2;
    const int tig = lane & 3;

    const int bn = blockIdx.x;
    const int bm = blockIdx.y;

    const uint4* gA = &gA_img[(size_t)bm * NKT * TILE_U4 + tid * 2];
    const uint4* gB = &gB_img[(size_t)bn * NKT * TILE_U4 + tid * 2];

    const uint32_t sBase = smem_u32(&smem[0][0]);
    // per-thread smem targets within a stage
    const uint32_t smA_off = (uint32_t)(tid * 32);            // 2 uint4
    const uint32_t smB_off = (uint32_t)(8192 + tid * 32);

    // ldmatrix lane geometry (A consumer)
    const int lrow = lane & 15;
    const int lkc  = lane >> 4;
    const int lsw  = (lrow >> 1) & 3;

    float acc[4][4][4];
#pragma unroll
    for (int mt = 0; mt < 4; mt++)
#pragma unroll
        for (int nt = 0; nt < 4; nt++)
#pragma unroll
            for (int c = 0; c < 4; c++) acc[mt][nt][c] = 0.f;

    auto issue = [&](int kt, int stage) {
        const uint32_t sa = sBase + stage * 16384 + smA_off;
        const uint32_t sb = sBase + stage * 16384 + smB_off;
        const uint4* ga = gA + (size_t)kt * TILE_U4;
        const uint4* gb = gB + (size_t)kt * TILE_U4;
        cp16(sa,      ga);
        cp16(sa + 16, ga + 1);
        cp16(sb,      gb);
        cp16(sb + 16, gb + 1);
        cp_commit();
    };

    // prologue: fill 2 stages
    issue(0, 0);
    issue(1, 1);

#pragma unroll 1
    for (int kt = 0; kt < NKT; ++kt) {
        const int stage = kt % STAGES;

        // Drain the group carrying tile kt. In steady state two groups are
        // outstanding (kt, kt+1) -> wait_group 1. On the FINAL iteration only
        // tile kt's group remains -> wait_group 0 (wait_group 1 would skip it
        // and consume a stale tile: that was the R7 correctness bug).
        if (kt == NKT - 1) cp_wait0(); else cp_wait1();
        __syncthreads();

        const uint32_t aBase = sBase + stage * 16384;
        const uint32_t* sBw = reinterpret_cast<const uint32_t*>(
            &smem[stage][TILE_U4]);

#pragma unroll
        for (int ks = 0; ks < 2; ++ks) {
            uint32_t af[4][4];
#pragma unroll
            for (int mt = 0; mt < 4; mt++) {
                const int row_g = warp_m * 64 + mt * 16 + lrow;
                const int qp = (ks * 2 + lkc) ^ lsw;
                ldsm4(af[mt], aBase + (uint32_t)(row_g * 64 + qp * 16));
            }
#pragma unroll
            for (int nt = 0; nt < 4; nt++) {
                const int col = warp_n * 32 + nt * 8 + gid;
                const int q0 = ks * 8 + tig;
                const int widx = q0 * 128 + (col ^ (tig << 3));
                const uint32_t b0 = sBw[widx];
                const uint32_t b1 = sBw[widx + 4 * 128];
#pragma unroll
                for (int mt = 0; mt < 4; mt++)
                    mma16816(acc[mt][nt], af[mt], b0, b1);
            }
        }

        if (kt + 2 < NKT) issue(kt + 2, (kt + 2) % STAGES);
    }

    // ---- epilogue: float2 stores ----
    const int bm0 = bm * BM, bn0 = bn * BN;
#pragma unroll
    for (int mt = 0; mt < 4; mt++) {
        const int row = bm0 + warp_m * 64 + mt * 16 + gid;
#pragma unroll
        for (int nt = 0; nt < 4; nt++) {
            const int col = bn0 + warp_n * 32 + nt * 8 + tig * 2;
            *reinterpret_cast<float2*>(&out[(size_t)row * OUT_DIM + col]) =
                make_float2(acc[mt][nt][0], acc[mt][nt][1]);
            *reinterpret_cast<float2*>(&out[(size_t)(row + 8) * OUT_DIM + col]) =
                make_float2(acc[mt][nt][2], acc[mt][nt][3]);
        }
    }
}

// ---------------------------------------------------------------------------
// Launch
// ---------------------------------------------------------------------------
extern "C" void kernel_launch(void* const* d_in, const int* in_sizes, int n_in,
                              void* d_out, int out_size) {
    const float* x    = (const float*)d_in[0];   // [8192, 1024] f32
    const float* rng  = (const float*)d_in[1];   // scalar f32
    const float* coef = (const float*)d_in[2];   // [1024, 1024, 8] f32
    float* out        = (float*)d_out;           // [8192, 1024] f32

    (void)in_sizes; (void)n_in; (void)out_size;

    // 1) prep A-tile images (tanh + powers, fp16, swizzled)
    {
        dim3 grid(NKT, NBM);   // (256, 64)
        prep_a_kernel<<<grid, 512>>>(x, rng);
    }
    // 2) prep B-tile images (coef -> fp16 k-paired, swizzled)
    {
        dim3 grid(NKT, NBN);   // (256, 8)
        prep_b_kernel<<<grid, 512>>>(coef);
    }
    // 3) pipelined fp16 tensor-core GEMM
    {
        dim3 grid(NBN, NBM);   // (8, 64)
        taylor_pipe_kernel<<<grid, 256>>>(out);
    }
}

// round 9
// speedup vs baseline: 8.9344x; 1.1664x over previous
#include <cuda_runtime.h>
#include <cuda_fp16.h>
#include <cstdint>

// Problem constants
#define B_DIM   8192
#define IN_DIM  1024
#define OUT_DIM 1024
#define ORD     8              // ORDER+1 powers per input
#define KTOT    (IN_DIM * ORD) // 8192 reduction length

#define BM 128
#define BN 128
#define BK 32                  // 4 inputs * 8 powers per K-tile
#define NKT (KTOT / BK)        // 256 K-tiles
#define NBM (B_DIM / BM)       // 64
#define NBN (OUT_DIM / BN)     // 8

#define STAGES 3
#define TILE_U4 512            // 8 KB per operand tile = 512 uint4

// Precomputed smem-image scratch
//   gA_img[bm][kt] = 8 KB A-tile image (quad-swizzled fp16 powers)   -> 128 MB
//   gB_img[bn][kt] = 8 KB B-tile image (xor-swizzled k-paired half2) ->  16 MB
__device__ __align__(16) uint4 gA_img[(size_t)NBM * NKT * TILE_U4];
__device__ __align__(16) uint4 gB_img[(size_t)NBN * NKT * TILE_U4];

// ---------------------------------------------------------------------------
// Helpers
// ---------------------------------------------------------------------------
__device__ __forceinline__ uint32_t smem_u32(const void* p) {
    uint32_t a;
    asm("{ .reg .u64 t; cvta.to.shared.u64 t, %1; cvt.u32.u64 %0, t; }"
        : "=r"(a) : "l"(p));
    return a;
}
__device__ __forceinline__ uint32_t packh2(float lo, float hi) {
    __half2 h = __floats2half2_rn(lo, hi);
    return *reinterpret_cast<uint32_t*>(&h);
}
__device__ __forceinline__ float tanh_fast(float x) {
    float r;
    asm("tanh.approx.f32 %0, %1;" : "=f"(r) : "f"(x));
    return r;
}
__device__ __forceinline__ void ldsm4(uint32_t* f, uint32_t addr) {
    asm volatile("ldmatrix.sync.aligned.m8n8.x4.shared.b16 {%0,%1,%2,%3}, [%4];"
                 : "=r"(f[0]), "=r"(f[1]), "=r"(f[2]), "=r"(f[3])
                 : "r"(addr) : "memory");
}
__device__ __forceinline__ void mma16816(float* c, const uint32_t* a,
                                         uint32_t b0, uint32_t b1) {
    asm("mma.sync.aligned.m16n8k16.row.col.f32.f16.f16.f32 "
        "{%0,%1,%2,%3}, {%4,%5,%6,%7}, {%8,%9}, {%0,%1,%2,%3};"
        : "+f"(c[0]), "+f"(c[1]), "+f"(c[2]), "+f"(c[3])
        : "r"(a[0]), "r"(a[1]), "r"(a[2]), "r"(a[3]), "r"(b0), "r"(b1));
}
__device__ __forceinline__ void cp16(uint32_t smaddr, const void* g) {
    asm volatile("cp.async.cg.shared.global [%0], [%1], 16;"
                 :: "r"(smaddr), "l"(g) : "memory");
}
__device__ __forceinline__ void cp_commit() {
    asm volatile("cp.async.commit_group;" ::: "memory");
}
__device__ __forceinline__ void cp_wait1() {
    asm volatile("cp.async.wait_group 1;" ::: "memory");
}
__device__ __forceinline__ void cp_wait0() {
    asm volatile("cp.async.wait_group 0;" ::: "memory");
}

// ---------------------------------------------------------------------------
// Prep kernel A: tanh + powers -> quad-swizzled fp16 tile image
//   image uint4 idx (in tile): row*4 + (q ^ ((row>>1)&3))
//   content: half2 pairs {1,t},{t2,t3},{t4,t5},{t6,t7} of t = tanh(x*r)
// ---------------------------------------------------------------------------
__global__ void prep_a_kernel(const float* __restrict__ x,
                              const float* __restrict__ rp) {
    const float r = *rp;
    const int kt = blockIdx.x;
    const int bm = blockIdx.y;
    const int tid = threadIdx.x;
    const int row = tid >> 2;
    const int q   = tid & 3;

    const float xv = x[(size_t)(bm * BM + row) * IN_DIM + kt * 4 + q];
    const float t  = tanh_fast(xv * r);
    const float t2 = t * t, t3 = t2 * t, t4 = t2 * t2;
    const float t5 = t4 * t, t6 = t3 * t3, t7 = t4 * t3;

    uint4 qv;
    qv.x = packh2(1.f, t);  qv.y = packh2(t2, t3);
    qv.z = packh2(t4, t5);  qv.w = packh2(t6, t7);

    gA_img[((size_t)bm * NKT + kt) * TILE_U4 + row * 4 + (q ^ ((row >> 1) & 3))] = qv;
}

// ---------------------------------------------------------------------------
// Prep kernel B: coef -> xor-swizzled k-paired half2 tile image
//   word idx (in tile): q0*128 + (j ^ ((q0&3)<<3)), q0 = k-pair index 0..15
//   content: half2(coef[j][kt*32+2*q0], coef[j][kt*32+2*q0+1])
// ---------------------------------------------------------------------------
__global__ void prep_b_kernel(const float* __restrict__ coef) {
    const int kt = blockIdx.x;
    const int bn = blockIdx.y;
    const int tid = threadIdx.x;
    const int s = tid & 3;        // k-octet slot (8 floats)
    const int j = tid >> 2;       // column 0..127

    const float* cp = &coef[(size_t)(bn * BN + j) * KTOT + kt * BK + s * 8];
    const float4 c0 = *reinterpret_cast<const float4*>(cp);
    const float4 c1 = *reinterpret_cast<const float4*>(cp + 4);

    uint32_t* gw = reinterpret_cast<uint32_t*>(
        &gB_img[((size_t)bn * NKT + kt) * TILE_U4]);
    const int q0 = s * 4;         // q0&3 == u for u = 0..3
    gw[(q0 + 0) * 128 + (j ^ 0)]  = packh2(c0.x, c0.y);
    gw[(q0 + 1) * 128 + (j ^ 8)]  = packh2(c0.z, c0.w);
    gw[(q0 + 2) * 128 + (j ^ 16)] = packh2(c1.x, c1.y);
    gw[(q0 + 3) * 128 + (j ^ 24)] = packh2(c1.z, c1.w);
}

// ---------------------------------------------------------------------------
// GEMM kernel: 3-stage cp.async fp16 m16n8k16 pipeline
// 128 threads = 4 warps, 2x2 over the 128x128 block tile, 64x64 per warp.
// smem stage layout: [A tile 8KB][B tile 8KB] per stage, 48 KB total.
// ---------------------------------------------------------------------------
__global__ __launch_bounds__(128, 2)
void taylor_pipe_kernel(float* __restrict__ out) {
    __shared__ __align__(16) uint4 smem[STAGES][2 * TILE_U4];

    const int tid  = threadIdx.x;
    const int lane = tid & 31;
    const int warp = tid >> 5;
    const int warp_m = warp >> 1;   // 2 warps over M (64 rows each)
    const int warp_n = warp & 1;    // 2 warps over N (64 cols each)
    const int gid = lane >> 2;
    const int tig = lane & 3;

    const int bn = blockIdx.x;
    const int bm = blockIdx.y;

    const uint4* gA = &gA_img[(size_t)bm * NKT * TILE_U4 + tid * 4];
    const uint4* gB = &gB_img[(size_t)bn * NKT * TILE_U4 + tid * 4];

    const uint32_t sBase = smem_u32(&smem[0][0]);
    // per-thread smem targets within a stage (4 uint4 each operand)
    const uint32_t smA_off = (uint32_t)(tid * 64);
    const uint32_t smB_off = (uint32_t)(8192 + tid * 64);

    // ldmatrix lane geometry (A consumer)
    const int lrow = lane & 15;
    const int lkc  = lane >> 4;
    const int lsw  = (lrow >> 1) & 3;

    float acc[4][8][4];
#pragma unroll
    for (int mt = 0; mt < 4; mt++)
#pragma unroll
        for (int nt = 0; nt < 8; nt++)
#pragma unroll
            for (int c = 0; c < 4; c++) acc[mt][nt][c] = 0.f;

    auto issue = [&](int kt, int stage) {
        const uint32_t sa = sBase + stage * 16384 + smA_off;
        const uint32_t sb = sBase + stage * 16384 + smB_off;
        const uint4* ga = gA + (size_t)kt * TILE_U4;
        const uint4* gb = gB + (size_t)kt * TILE_U4;
#pragma unroll
        for (int u = 0; u < 4; u++) {
            cp16(sa + u * 16, ga + u);
            cp16(sb + u * 16, gb + u);
        }
        cp_commit();
    };

    // prologue: fill 2 stages
    issue(0, 0);
    issue(1, 1);

#pragma unroll 1
    for (int kt = 0; kt < NKT; ++kt) {
        const int stage = kt % STAGES;

        // Drain the group carrying tile kt. Steady state: two groups
        // outstanding -> wait_group 1. Final iteration: only one left ->
        // wait_group 0 (wait_group 1 would consume a stale tile).
        if (kt == NKT - 1) cp_wait0(); else cp_wait1();
        __syncthreads();

        const uint32_t aBase = sBase + stage * 16384;
        const uint32_t* sBw = reinterpret_cast<const uint32_t*>(
            &smem[stage][TILE_U4]);

#pragma unroll
        for (int ks = 0; ks < 2; ++ks) {
            uint32_t af[4][4];
#pragma unroll
            for (int mt = 0; mt < 4; mt++) {
                const int row_g = warp_m * 64 + mt * 16 + lrow;
                const int qp = (ks * 2 + lkc) ^ lsw;
                ldsm4(af[mt], aBase + (uint32_t)(row_g * 64 + qp * 16));
            }
#pragma unroll
            for (int nt = 0; nt < 8; nt++) {
                const int col = warp_n * 64 + nt * 8 + gid;
                const int q0 = ks * 8 + tig;
                const int widx = q0 * 128 + (col ^ (tig << 3));
                const uint32_t b0 = sBw[widx];
                const uint32_t b1 = sBw[widx + 4 * 128];
#pragma unroll
                for (int mt = 0; mt < 4; mt++)
                    mma16816(acc[mt][nt], af[mt], b0, b1);
            }
        }

        if (kt + 2 < NKT) issue(kt + 2, (kt + 2) % STAGES);
    }

    // ---- epilogue: float2 stores ----
    const int bm0 = bm * BM, bn0 = bn * BN;
#pragma unroll
    for (int mt = 0; mt < 4; mt++) {
        const int row = bm0 + warp_m * 64 + mt * 16 + gid;
#pragma unroll
        for (int nt = 0; nt < 8; nt++) {
            const int col = bn0 + warp_n * 64 + nt * 8 + tig * 2;
            *reinterpret_cast<float2*>(&out[(size_t)row * OUT_DIM + col]) =
                make_float2(acc[mt][nt][0], acc[mt][nt][1]);
            *reinterpret_cast<float2*>(&out[(size_t)(row + 8) * OUT_DIM + col]) =
                make_float2(acc[mt][nt][2], acc[mt][nt][3]);
        }
    }
}

// ---------------------------------------------------------------------------
// Launch
// ---------------------------------------------------------------------------
extern "C" void kernel_launch(void* const* d_in, const int* in_sizes, int n_in,
                              void* d_out, int out_size) {
    const float* x    = (const float*)d_in[0];   // [8192, 1024] f32
    const float* rng  = (const float*)d_in[1];   // scalar f32
    const float* coef = (const float*)d_in[2];   // [1024, 1024, 8] f32
    float* out        = (float*)d_out;           // [8192, 1024] f32

    (void)in_sizes; (void)n_in; (void)out_size;

    // 1) prep A-tile images (tanh + powers, fp16, swizzled)
    {
        dim3 grid(NKT, NBM);   // (256, 64)
        prep_a_kernel<<<grid, 512>>>(x, rng);
    }
    // 2) prep B-tile images (coef -> fp16 k-paired, swizzled)
    {
        dim3 grid(NKT, NBN);   // (256, 8)
        prep_b_kernel<<<grid, 512>>>(coef);
    }
    // 3) pipelined fp16 tensor-core GEMM (4 warps, 64x64 warp tiles)
    {
        dim3 grid(NBN, NBM);   // (8, 64)
        taylor_pipe_kernel<<<grid, 128>>>(out);
    }
}